// round 13
// baseline (speedup 1.0000x reference)
#include <cuda_runtime.h>
#include <math.h>

#define BB 64
#define LQ 32
#define OO 128
#define LK 256
#define DD 128
#define ALPHA_F 12.0f
#define NPAIRS (BB * OO)   // 8192
#define GRID_SCORE 304
#define PREP_BLOCKS 512
#define KCH 64             // k rows per chunk
#define KSTF 132           // floats per k row in smem (pad: conflict-free LDS.128)
#define KBUF (KCH * KSTF)  // floats per k buffer

typedef unsigned long long ull;

// ---------------- scratch (no allocations allowed) ----------------
__device__ float g_rq[BB * LQ];    // 1/max(||q_row||,1e-12)
__device__ float g_rk[OO * LK];    // 1/max(||k_row||,1e-12)
__device__ unsigned g_part[4][32]; // mask dtype scan partials (always rewritten)

// ---------------- packed f32x2 helpers (sm_103a FFMA2) ----------------
__device__ __forceinline__ ull dup2(float x) {
    ull r;
    unsigned xi = __float_as_uint(x);
    asm("mov.b64 %0, {%1, %1};" : "=l"(r) : "r"(xi));
    return r;
}
__device__ __forceinline__ void fma2(ull& d, ull a, ull b) {
    asm("fma.rn.f32x2 %0, %1, %2, %0;" : "+l"(d) : "l"(a), "l"(b));
}
__device__ __forceinline__ ull pack2(float lo, float hi) {
    ull r;
    asm("mov.b64 %0, {%1, %2};" : "=l"(r)
        : "r"(__float_as_uint(lo)), "r"(__float_as_uint(hi)));
    return r;
}
__device__ __forceinline__ void unpack2(float& lo, float& hi, ull v) {
    unsigned a, b;
    asm("mov.b64 {%0, %1}, %2;" : "=r"(a), "=r"(b) : "l"(v));
    lo = __uint_as_float(a);
    hi = __uint_as_float(b);
}

// ---------------- cp.async helpers ----------------
__device__ __forceinline__ unsigned smem_u32(const void* p) {
    return (unsigned)__cvta_generic_to_shared(p);
}
#define CP_ASYNC16(dst, src) \
    asm volatile("cp.async.cg.shared.global [%0], [%1], 16;" ::"r"(dst), "l"(src))
#define CP_COMMIT() asm volatile("cp.async.commit_group;")
#define CP_WAIT1() asm volatile("cp.async.wait_group 1;" ::: "memory")
#define CP_WAIT0() asm volatile("cp.async.wait_group 0;" ::: "memory")

// ============ kernel 1: prep ==========================================
// 512 blocks x 256. Computes all q/k row rinvs (one DRAM pass, warms L2),
// zero-fills out, and (blocks 0..31) the mask-dtype scan partials.
// Masks may arrive as 1-byte bool or int32 (0/1). Under little-endian
// int32 storage, bytes at i%4!=0 within the first N bytes are all zero;
// under u8 bool with ~10% ones, off-bytes are nonzero in practice. Reading
// only the first N bytes is safe under both interpretations.
__global__ void __launch_bounds__(256)
prep_kernel(const float* __restrict__ q, const float* __restrict__ k,
            const void* __restrict__ qm_raw, const void* __restrict__ km_raw,
            float* __restrict__ out) {
    const int tid = threadIdx.x, lane = tid & 31, w = tid >> 5;
    const int gw = blockIdx.x * 8 + w;  // global warp 0..4095
    const int gid = blockIdx.x * 256 + tid;

    if (gid < NPAIRS) out[gid] = 0.0f;  // masked pairs stay 0; score overwrites live

    // q rinvs: one row per warp (2048 rows)
    if (gw < BB * LQ) {
        float4 v = *((const float4*)(q + (size_t)gw * DD + lane * 4));
        float ss = v.x * v.x + v.y * v.y + v.z * v.z + v.w * v.w;
#pragma unroll
        for (int off = 16; off; off >>= 1)
            ss += __shfl_xor_sync(0xffffffffu, ss, off);
        if (lane == 0) g_rq[gw] = 1.0f / fmaxf(sqrtf(ss), 1e-12f);
    }
    // k rinvs: 8 rows per warp (32768 rows)
#pragma unroll
    for (int r = 0; r < 8; r++) {
        int row = gw + 4096 * r;
        float4 v = *((const float4*)(k + (size_t)row * DD + lane * 4));
        float ss = v.x * v.x + v.y * v.y + v.z * v.z + v.w * v.w;
#pragma unroll
        for (int off = 16; off; off >>= 1)
            ss += __shfl_xor_sync(0xffffffffu, ss, off);
        if (lane == 0) g_rk[row] = 1.0f / fmaxf(sqrtf(ss), 1e-12f);
    }

    // mask dtype scan partials (blocks 0..31)
    if (blockIdx.x < 32) {
        unsigned f[4] = {0u, 0u, 0u, 0u};
        const uint4* qv = (const uint4*)qm_raw;
        const uint4* kv = (const uint4*)km_raw;
        for (int i = gid; i < (BB * LQ) / 16; i += 8192) {
            uint4 v = qv[i];
            unsigned o = v.x | v.y | v.z | v.w;
            f[0] |= o & 0xFFFFFF00u;
            f[1] |= o & 0xFFu;
        }
        for (int i = gid; i < (OO * LK) / 16; i += 8192) {
            uint4 v = kv[i];
            unsigned o = v.x | v.y | v.z | v.w;
            f[2] |= o & 0xFFFFFF00u;
            f[3] |= o & 0xFFu;
        }
#pragma unroll
        for (int ff = 0; ff < 4; ff++)
#pragma unroll
            for (int off = 16; off; off >>= 1)
                f[ff] |= __shfl_xor_sync(0xffffffffu, f[ff], off);
        __shared__ unsigned wf[4][8];
        if (lane == 0) {
#pragma unroll
            for (int ff = 0; ff < 4; ff++) wf[ff][w] = f[ff];
        }
        __syncthreads();
        if (tid < 4) {
            unsigned r = 0u;
#pragma unroll
            for (int ww = 0; ww < 8; ww++) r |= wf[tid][ww];
            g_part[tid][blockIdx.x] = r;
        }
    }
}

// online logsumexp fold
__device__ __forceinline__ void lse_fold(float& m, float& s, float v) {
    float mn = fmaxf(m, v);
    if (mn != -INFINITY) {
        float e1 = __expf(m - mn);                       // m=-inf -> 0
        float e2 = (v == -INFINITY) ? 0.0f : __expf(v - mn);
        s = s * e1 + e2;
        m = mn;
    }
}

// ============ kernel 2: score =========================================
// 304 blocks x 256. Preamble resolves mask dtype + compacts clean batches
// (any masked q token => whole output row exactly 0: the Lq-sum hits -inf).
// Grid-stride over live pairs only (typically <= grid => <=1 heavy pair
// per block). Per pair: q rows packed in f32x2 pairs in smem; 64-row k
// chunks double-buffered via cp.async; dot products via fma.rn.f32x2
// (FFMA2, 2 MACs/instr); precomputed rinvs folded into the logit scale
// after the dot; online logsumexp over Lk.
// Warp w: q rows (w&3)*8..+8 (4 packed pairs), j-half (w>>2), 1 col/lane.
__global__ void __launch_bounds__(256, 2)
score_kernel(const float* __restrict__ q, const float* __restrict__ k,
             const void* __restrict__ qm_raw, const void* __restrict__ km_raw,
             const float* __restrict__ ls, float* __restrict__ out) {
    const int tid = threadIdx.x;
    const int w = tid >> 5, lane = tid & 31;

    __shared__ unsigned s_flags[4];
    __shared__ int s_k_u8, s_q_u8, s_nclean;
    __shared__ float s_outscale;
    __shared__ unsigned char s_bad[BB];
    __shared__ unsigned char s_list[BB];
    __shared__ float sm_m[8][8], sm_s[8][8];

    if (tid < 128) {  // reduce the 32 partial slots; warp per flag
        unsigned v = g_part[w][lane];
#pragma unroll
        for (int off = 16; off; off >>= 1)
            v |= __shfl_xor_sync(0xffffffffu, v, off);
        if (lane == 0) s_flags[w] = v;
    }
    __syncthreads();
    if (tid == 0) {
        // nonzero off-bytes => u8; only aligned nonzeros => int32; zero => u8
        s_q_u8 = ((s_flags[0] != 0u) || (s_flags[1] == 0u)) ? 1 : 0;
        s_k_u8 = ((s_flags[2] != 0u) || (s_flags[3] == 0u)) ? 1 : 0;
        float e = fminf(__expf(ls[0]), 100.0f);
        s_outscale = e / (sqrtf((float)(LQ * LK)) + 1e-6f);
    }
    __syncthreads();
    if (tid < BB) {  // per-batch "has masked q" (dtype-safe reads only)
        unsigned acc;
        if (s_q_u8) {
            const uint4* p = (const uint4*)qm_raw;  // 32 B = 2 uint4 / batch
            uint4 a = p[tid * 2], c = p[tid * 2 + 1];
            acc = a.x | a.y | a.z | a.w | c.x | c.y | c.z | c.w;
        } else {
            const uint4* p = (const uint4*)qm_raw;  // 128 B = 8 uint4 / batch
            acc = 0u;
#pragma unroll
            for (int i = 0; i < 8; i++) {
                uint4 v = p[tid * 8 + i];
                acc |= v.x | v.y | v.z | v.w;
            }
        }
        s_bad[tid] = acc ? 1 : 0;
    }
    __syncthreads();
    if (tid == 0) {  // compact clean-batch list
        int n = 0;
        for (int b = 0; b < BB; b++)
            if (!s_bad[b]) s_list[n++] = (unsigned char)b;
        s_nclean = n;
    }
    __syncthreads();

    const int live = s_nclean * OO;
    const bool k_u8 = (s_k_u8 != 0);
    const float outscale = s_outscale;

    extern __shared__ float sm[];
    ull* qs2 = (ull*)sm;    // 16 pairs x 128 d, packed {row2p, row2p+1}
    float* ks = sm + 4096;  // 2 x (64 x 132) k buffers

    const int rg = w & 3;   // q row group (8 rows)
    const int jh = w >> 2;  // j half within a 64-row chunk

    for (int idx = blockIdx.x; idx < live; idx += GRID_SCORE) {
        const int b = s_list[idx >> 7];
        const int o = idx & (OO - 1);

        __syncthreads();  // prior pair's qs2/ks reads done
        {  // pack q rows in pairs: qs2[p][d] = {q[2p][d], q[2p+1][d]}
            const float4* q4 = (const float4*)(q + (size_t)b * LQ * DD);
            for (int i = tid; i < 512; i += 256) {
                int p = i >> 5, dc = i & 31;
                float4 va = q4[(2 * p) * 32 + dc];
                float4 vb = q4[(2 * p + 1) * 32 + dc];
                ull* dst = qs2 + p * 128 + dc * 4;
                dst[0] = pack2(va.x, vb.x);
                dst[1] = pack2(va.y, vb.y);
                dst[2] = pack2(va.z, vb.z);
                dst[3] = pack2(va.w, vb.w);
            }
        }
        // issue k chunks 0,1 (64 rows x 512 B each; 8 x 16B per thread)
#pragma unroll
        for (int c0 = 0; c0 < 2; c0++) {
            const float* src = k + ((size_t)o * LK + c0 * KCH) * DD;
            float* dbuf = ks + c0 * KBUF;
#pragma unroll
            for (int t2 = 0; t2 < 8; t2++) {
                int i = tid + t2 * 256;
                int row = i >> 5, seg = i & 31;
                CP_ASYNC16(smem_u32(dbuf + row * KSTF + seg * 4),
                           src + row * DD + seg * 4);
            }
            CP_COMMIT();
        }

        float rq8[8];
#pragma unroll
        for (int a = 0; a < 8; a++) rq8[a] = g_rq[b * LQ + rg * 8 + a];

        float m8[8], s8[8];
#pragma unroll
        for (int a = 0; a < 8; a++) { m8[a] = -INFINITY; s8[a] = 0.0f; }

#pragma unroll
        for (int ch = 0; ch < 4; ch++) {
            if (ch < 3) CP_WAIT1(); else CP_WAIT0();
            __syncthreads();  // chunk ch resident for all threads

            const float* kb = ks + (ch & 1) * KBUF;
            const int jloc = jh * 32 + lane;  // 0..63 in chunk
            const int j = ch * KCH + jloc;    // global k row for this o
            const float rk = g_rk[o * LK + j];
            const bool bad =
                k_u8 ? (((const unsigned char*)km_raw)[o * LK + j] != 0)
                     : (((const int*)km_raw)[o * LK + j] != 0);
            const float* krow = kb + jloc * KSTF;
            const ull* qw = qs2 + rg * 4 * 128;

            ull acc[4] = {0ull, 0ull, 0ull, 0ull};
            for (int d4 = 0; d4 < 32; d4++) {
                float4 kv = *((const float4*)(krow + d4 * 4));
                ull k0 = dup2(kv.x), k1 = dup2(kv.y);
                ull k2 = dup2(kv.z), k3 = dup2(kv.w);
#pragma unroll
                for (int ap = 0; ap < 4; ap++) {
                    const ull* qp = qw + ap * 128 + d4 * 4;
                    ulonglong2 qa = *((const ulonglong2*)qp);
                    ulonglong2 qb = *((const ulonglong2*)(qp + 2));
                    fma2(acc[ap], qa.x, k0);
                    fma2(acc[ap], qa.y, k1);
                    fma2(acc[ap], qb.x, k2);
                    fma2(acc[ap], qb.y, k3);
                }
            }
            // fold this chunk's single column into the lse stats
#pragma unroll
            for (int ap = 0; ap < 4; ap++) {
                float lo, hi;
                unpack2(lo, hi, acc[ap]);
                float v0 = bad ? -INFINITY : lo * (ALPHA_F * rq8[2 * ap] * rk);
                float v1 =
                    bad ? -INFINITY : hi * (ALPHA_F * rq8[2 * ap + 1] * rk);
                lse_fold(m8[2 * ap], s8[2 * ap], v0);
                lse_fold(m8[2 * ap + 1], s8[2 * ap + 1], v1);
            }
            __syncthreads();  // all reads of buf (ch&1) done
            if (ch < 2) {     // refill it with chunk ch+2
                const float* src = k + ((size_t)o * LK + (ch + 2) * KCH) * DD;
                float* dbuf = ks + (ch & 1) * KBUF;
#pragma unroll
                for (int t2 = 0; t2 < 8; t2++) {
                    int i = tid + t2 * 256;
                    int row = i >> 5, seg = i & 31;
                    CP_ASYNC16(smem_u32(dbuf + row * KSTF + seg * 4),
                               src + row * DD + seg * 4);
                }
                CP_COMMIT();
            }
        }

        // merge (m,s) across the 32 lanes of each warp (per row)
#pragma unroll
        for (int a = 0; a < 8; a++) {
            float m = m8[a], s = s8[a];
#pragma unroll
            for (int off = 16; off; off >>= 1) {
                float mo = __shfl_xor_sync(0xffffffffu, m, off);
                float so = __shfl_xor_sync(0xffffffffu, s, off);
                float mn = fmaxf(m, mo);
                if (mn == -INFINITY) {
                    m = -INFINITY;
                    s = 0.0f;
                } else {
                    s = s * __expf(m - mn) + so * __expf(mo - mn);
                    m = mn;
                }
            }
            m8[a] = m;
            s8[a] = s;
        }
        if (lane == 0) {
#pragma unroll
            for (int a = 0; a < 8; a++) {
                sm_m[w][a] = m8[a];
                sm_s[w][a] = s8[a];
            }
        }
        __syncthreads();
        if (tid < 32) {  // combine j-halves (warps rg & rg+4), sum 32 rows
            int rgr = tid >> 3, a = tid & 7;
            float m1 = sm_m[rgr][a], s1 = sm_s[rgr][a];
            float m2 = sm_m[rgr + 4][a], s2 = sm_s[rgr + 4][a];
            float mn = fmaxf(m1, m2);
            float lse;
            if (mn == -INFINITY)
                lse = -INFINITY;  // all-masked k row => whole (b,o) -> 0
            else
                lse = mn + __logf(s1 * __expf(m1 - mn) + s2 * __expf(m2 - mn));
            float tot = lse;
#pragma unroll
            for (int off = 16; off; off >>= 1)
                tot += __shfl_xor_sync(0xffffffffu, tot, off);
            if (tid == 0) {
                float res = isfinite(tot) ? (tot / ALPHA_F) * outscale : 0.0f;
                out[b * OO + o] = res;
            }
        }
    }
}

// ---------------- launch ----------------
extern "C" void kernel_launch(void* const* d_in, const int* in_sizes, int n_in,
                              void* d_out, int out_size) {
    const float* q = (const float*)d_in[0];
    const float* k = (const float*)d_in[1];
    const void* qm = d_in[2];
    const void* km = d_in[3];
    const float* ls = (const float*)d_in[4];
    float* out = (float*)d_out;

    prep_kernel<<<PREP_BLOCKS, 256>>>(q, k, qm, km, out);

    // qs2 16KB + 2 k buffers (64x132x4 x2) = 83968 B
    size_t smem = (size_t)(4096 + 2 * KBUF) * sizeof(float);
    cudaFuncSetAttribute(score_kernel,
                         cudaFuncAttributeMaxDynamicSharedMemorySize,
                         (int)smem);
    score_kernel<<<GRID_SCORE, 256, smem>>>(q, k, qm, km, ls, out);
}

// round 16
// speedup vs baseline: 1.3225x; 1.3225x over previous
#include <cuda_runtime.h>
#include <math.h>

#define BB 64
#define LQ 32
#define OO 128
#define LK 256
#define DD 128
#define ALPHA_F 12.0f
#define NPAIRS (BB * OO)    // 8192
#define PREP_BLOCKS 512
#define SCORE_BLOCKS 444    // ~3 CTAs/SM resident
#define KST 132             // floats per k row in smem (16B-aligned, conflict-free)

typedef unsigned long long ull;

// ---------------- scratch (no allocations allowed) ----------------
__device__ float g_rq[BB * LQ];    // 1/max(||q_row||,1e-12)
__device__ float g_rk[OO * LK];    // 1/max(||k_row||,1e-12)
__device__ unsigned g_part[4][32]; // mask dtype scan partials (always rewritten)
__device__ int g_ctr;              // work-steal counter (reset by prep)

// ---------------- packed f32x2 helpers (sm_103a FFMA2) ----------------
__device__ __forceinline__ ull dup2(float x) {
    ull r;
    unsigned xi = __float_as_uint(x);
    asm("mov.b64 %0, {%1, %1};" : "=l"(r) : "r"(xi));
    return r;
}
__device__ __forceinline__ void fma2(ull& d, ull a, ull b) {
    asm("fma.rn.f32x2 %0, %1, %2, %0;" : "+l"(d) : "l"(a), "l"(b));
}
__device__ __forceinline__ ull pack2(float lo, float hi) {
    ull r;
    asm("mov.b64 %0, {%1, %2};" : "=l"(r)
        : "r"(__float_as_uint(lo)), "r"(__float_as_uint(hi)));
    return r;
}
__device__ __forceinline__ void unpack2(float& lo, float& hi, ull v) {
    unsigned a, b;
    asm("mov.b64 {%0, %1}, %2;" : "=r"(a), "=r"(b) : "l"(v));
    lo = __uint_as_float(a);
    hi = __uint_as_float(b);
}

// ============ kernel 1: prep ==========================================
// 512 blocks x 256. Row rinvs for q/k (one DRAM pass, warms L2), zero-fills
// out, resets the steal counter, and (blocks 0..31) mask-dtype scan partials.
// Masks may arrive as 1-byte bool or int32 (0/1). Under little-endian int32
// storage, bytes at i%4!=0 within the first N bytes are all zero; under u8
// bool with ~10% ones, off-bytes are nonzero in practice. Reading only the
// first N bytes is safe under both interpretations.
__global__ void __launch_bounds__(256)
prep_kernel(const float* __restrict__ q, const float* __restrict__ k,
            const void* __restrict__ qm_raw, const void* __restrict__ km_raw,
            float* __restrict__ out) {
    const int tid = threadIdx.x, lane = tid & 31, w = tid >> 5;
    const int gw = blockIdx.x * 8 + w;  // global warp 0..4095
    const int gid = blockIdx.x * 256 + tid;

    if (gid == 0) g_ctr = 0;            // steal counter reset (each replay)
    if (gid < NPAIRS) out[gid] = 0.0f;  // score atomically accumulates on top

    // q rinvs: one row per warp (2048 rows)
    if (gw < BB * LQ) {
        float4 v = *((const float4*)(q + (size_t)gw * DD + lane * 4));
        float ss = v.x * v.x + v.y * v.y + v.z * v.z + v.w * v.w;
#pragma unroll
        for (int off = 16; off; off >>= 1)
            ss += __shfl_xor_sync(0xffffffffu, ss, off);
        if (lane == 0) g_rq[gw] = 1.0f / fmaxf(sqrtf(ss), 1e-12f);
    }
    // k rinvs: 8 rows per warp (32768 rows)
#pragma unroll
    for (int r = 0; r < 8; r++) {
        int row = gw + 4096 * r;
        float4 v = *((const float4*)(k + (size_t)row * DD + lane * 4));
        float ss = v.x * v.x + v.y * v.y + v.z * v.z + v.w * v.w;
#pragma unroll
        for (int off = 16; off; off >>= 1)
            ss += __shfl_xor_sync(0xffffffffu, ss, off);
        if (lane == 0) g_rk[row] = 1.0f / fmaxf(sqrtf(ss), 1e-12f);
    }

    // mask dtype scan partials (blocks 0..31)
    if (blockIdx.x < 32) {
        unsigned f[4] = {0u, 0u, 0u, 0u};
        const uint4* qv = (const uint4*)qm_raw;
        const uint4* kv = (const uint4*)km_raw;
        for (int i = gid; i < (BB * LQ) / 16; i += 8192) {
            uint4 v = qv[i];
            unsigned o = v.x | v.y | v.z | v.w;
            f[0] |= o & 0xFFFFFF00u;
            f[1] |= o & 0xFFu;
        }
        for (int i = gid; i < (OO * LK) / 16; i += 8192) {
            uint4 v = kv[i];
            unsigned o = v.x | v.y | v.z | v.w;
            f[2] |= o & 0xFFFFFF00u;
            f[3] |= o & 0xFFu;
        }
#pragma unroll
        for (int ff = 0; ff < 4; ff++)
#pragma unroll
            for (int off = 16; off; off >>= 1)
                f[ff] |= __shfl_xor_sync(0xffffffffu, f[ff], off);
        __shared__ unsigned wf[4][8];
        if (lane == 0) {
#pragma unroll
            for (int ff = 0; ff < 4; ff++) wf[ff][w] = f[ff];
        }
        __syncthreads();
        if (tid < 4) {
            unsigned r = 0u;
#pragma unroll
            for (int ww = 0; ww < 8; ww++) r |= wf[tid][ww];
            g_part[tid][blockIdx.x] = r;
        }
    }
}

// online logsumexp fold
__device__ __forceinline__ void lse_fold(float& m, float& s, float v) {
    float mn = fmaxf(m, v);
    if (mn != -INFINITY) {
        float e1 = __expf(m - mn);  // m=-inf -> 0
        float e2 = (v == -INFINITY) ? 0.0f : __expf(v - mn);
        s = s * e1 + e2;
        m = mn;
    }
}

// ============ kernel 2: score =========================================
// 444 persistent blocks x 128 threads (4 warps). Preamble resolves mask
// dtype + compacts clean batches (any masked q token => whole output row
// exactly 0: the Lq-sum hits -inf). Work unit = (clean b, o, 16-row half),
// pulled from a global atomic counter for near-perfect balance. Each warp
// owns 2 q row-pairs (4 rows); each lane 4 j columns per 128-j chunk.
// Dot products via fma.rn.f32x2 (2 MACs/instr); precomputed rinvs folded
// into the logit scale post-dot; online logsumexp over Lk; the two halves
// of a pair merge by atomicAdd into the prep-zeroed output (2 commutative
// fp adds -> replay-deterministic). If every j of this o is masked, the
// block skips the add (result must be exactly 0).
__global__ void __launch_bounds__(128, 3)
score_kernel(const float* __restrict__ q, const float* __restrict__ k,
             const void* __restrict__ qm_raw, const void* __restrict__ km_raw,
             const float* __restrict__ ls, float* __restrict__ out) {
    const int tid = threadIdx.x;
    const int w = tid >> 5, lane = tid & 31;

    __shared__ unsigned s_flags[4];
    __shared__ int s_k_u8, s_q_u8, s_nclean, s_idx;
    __shared__ float s_outscale;
    __shared__ unsigned char s_bad[BB];
    __shared__ unsigned char s_list[BB];
    __shared__ float wsum[4];

    {  // reduce the 32 partial dtype slots; one warp per flag
        unsigned v = g_part[w][lane];
#pragma unroll
        for (int off = 16; off; off >>= 1)
            v |= __shfl_xor_sync(0xffffffffu, v, off);
        if (lane == 0) s_flags[w] = v;
    }
    __syncthreads();
    if (tid == 0) {
        // nonzero off-bytes => u8; only aligned nonzeros => int32; zero => u8
        s_q_u8 = ((s_flags[0] != 0u) || (s_flags[1] == 0u)) ? 1 : 0;
        s_k_u8 = ((s_flags[2] != 0u) || (s_flags[3] == 0u)) ? 1 : 0;
        float e = fminf(__expf(ls[0]), 100.0f);
        s_outscale = e / (sqrtf((float)(LQ * LK)) + 1e-6f);
    }
    __syncthreads();
    if (tid < BB) {  // per-batch "has masked q" (dtype-safe reads only)
        unsigned acc;
        if (s_q_u8) {
            const uint4* p = (const uint4*)qm_raw;  // 32 B = 2 uint4 / batch
            uint4 a = p[tid * 2], c = p[tid * 2 + 1];
            acc = a.x | a.y | a.z | a.w | c.x | c.y | c.z | c.w;
        } else {
            const uint4* p = (const uint4*)qm_raw;  // 128 B = 8 uint4 / batch
            acc = 0u;
#pragma unroll
            for (int i = 0; i < 8; i++) {
                uint4 v = p[tid * 8 + i];
                acc |= v.x | v.y | v.z | v.w;
            }
        }
        s_bad[tid] = acc ? 1 : 0;
    }
    __syncthreads();
    if (tid == 0) {  // compact clean-batch list
        int n = 0;
        for (int b = 0; b < BB; b++)
            if (!s_bad[b]) s_list[n++] = (unsigned char)b;
        s_nclean = n;
    }
    __syncthreads();

    const int n_units = s_nclean * OO * 2;
    const bool k_u8 = (s_k_u8 != 0);
    const float outscale = s_outscale;

    extern __shared__ float sm[];
    ull* qs2 = (ull*)sm;    // 8 pairs x 128 d, packed {row 2P, row 2P+1}
    float* ks = sm + 2048;  // 128 x 132 k chunk

    while (true) {
        __syncthreads();  // prior unit's smem reads done; s_idx reusable
        if (tid == 0) s_idx = atomicAdd(&g_ctr, 1);
        __syncthreads();
        const int idx = s_idx;
        if (idx >= n_units) break;  // uniform exit

        const int h = idx & 1;            // 16-row half
        const int o = (idx >> 1) & (OO - 1);
        const int b = s_list[idx >> 8];

        {  // pack this half's q rows in pairs: qs2[p][d] = {q[2p][d], q[2p+1][d]}
            const float4* q4 = (const float4*)(q + ((size_t)b * LQ + h * 16) * DD);
            for (int i = tid; i < 256; i += 128) {
                int p = i >> 5, dc = i & 31;
                float4 va = q4[(2 * p) * 32 + dc];
                float4 vb = q4[(2 * p + 1) * 32 + dc];
                ull* dst = qs2 + p * 128 + dc * 4;
                dst[0] = pack2(va.x, vb.x);
                dst[1] = pack2(va.y, vb.y);
                dst[2] = pack2(va.z, vb.z);
                dst[3] = pack2(va.w, vb.w);
            }
        }

        float rqv[4];  // warp's 4 rows: h*16 + 4w + a
#pragma unroll
        for (int a = 0; a < 4; a++)
            rqv[a] = g_rq[b * LQ + h * 16 + 4 * w + a];

        float m4[4], s4[4];
#pragma unroll
        for (int a = 0; a < 4; a++) { m4[a] = -INFINITY; s4[a] = 0.0f; }
        int my_clear = 0;

#pragma unroll
        for (int ch = 0; ch < 2; ch++) {
            __syncthreads();  // prev chunk reads done (and q writes ordered)
            {  // load 128-j chunk (coalesced float4, L2-resident)
                const float4* src =
                    (const float4*)(k + ((size_t)o * LK + ch * 128) * DD);
                for (int t = tid; t < 128 * 32; t += 128) {
                    int rr = t >> 5, cc = t & 31;
                    float4 v = src[t];
                    *((float4*)(ks + rr * KST + cc * 4)) = v;
                }
            }
            __syncthreads();

            float rk4[4];
            bool bad4[4];
#pragma unroll
            for (int c = 0; c < 4; c++) {
                const int j = ch * 128 + lane + 32 * c;
                rk4[c] = g_rk[o * LK + j];
                bad4[c] =
                    k_u8 ? (((const unsigned char*)km_raw)[o * LK + j] != 0)
                         : (((const int*)km_raw)[o * LK + j] != 0);
                my_clear |= bad4[c] ? 0 : 1;
            }

            ull acc[2][4];
#pragma unroll
            for (int pp = 0; pp < 2; pp++)
#pragma unroll
                for (int c = 0; c < 4; c++) acc[pp][c] = 0ull;

            const ull* qp0 = qs2 + (2 * w) * 128;
            const ull* qp1 = qs2 + (2 * w + 1) * 128;

            for (int d4 = 0; d4 < 32; d4++) {
                float4 kv0 = *((const float4*)(ks + lane * KST + d4 * 4));
                float4 kv1 = *((const float4*)(ks + (lane + 32) * KST + d4 * 4));
                float4 kv2 = *((const float4*)(ks + (lane + 64) * KST + d4 * 4));
                float4 kv3 = *((const float4*)(ks + (lane + 96) * KST + d4 * 4));
                ulonglong2 qa0 = *((const ulonglong2*)(qp0 + d4 * 4));
                ulonglong2 qb0 = *((const ulonglong2*)(qp0 + d4 * 4 + 2));
                ulonglong2 qa1 = *((const ulonglong2*)(qp1 + d4 * 4));
                ulonglong2 qb1 = *((const ulonglong2*)(qp1 + d4 * 4 + 2));
#define DSTEP(Q0, Q1, X0, X1, X2, X3)                         \
                {                                              \
                    ull kd0 = dup2(X0), kd1 = dup2(X1);        \
                    ull kd2 = dup2(X2), kd3 = dup2(X3);        \
                    fma2(acc[0][0], Q0, kd0);                  \
                    fma2(acc[0][1], Q0, kd1);                  \
                    fma2(acc[0][2], Q0, kd2);                  \
                    fma2(acc[0][3], Q0, kd3);                  \
                    fma2(acc[1][0], Q1, kd0);                  \
                    fma2(acc[1][1], Q1, kd1);                  \
                    fma2(acc[1][2], Q1, kd2);                  \
                    fma2(acc[1][3], Q1, kd3);                  \
                }
                DSTEP(qa0.x, qa1.x, kv0.x, kv1.x, kv2.x, kv3.x)
                DSTEP(qa0.y, qa1.y, kv0.y, kv1.y, kv2.y, kv3.y)
                DSTEP(qb0.x, qb1.x, kv0.z, kv1.z, kv2.z, kv3.z)
                DSTEP(qb0.y, qb1.y, kv0.w, kv1.w, kv2.w, kv3.w)
#undef DSTEP
            }

            // fold this chunk's 4 columns into the lse stats
#pragma unroll
            for (int c = 0; c < 4; c++) {
                float lo, hi, v;
                unpack2(lo, hi, acc[0][c]);
                v = bad4[c] ? -INFINITY : lo * (ALPHA_F * rqv[0] * rk4[c]);
                lse_fold(m4[0], s4[0], v);
                v = bad4[c] ? -INFINITY : hi * (ALPHA_F * rqv[1] * rk4[c]);
                lse_fold(m4[1], s4[1], v);
                unpack2(lo, hi, acc[1][c]);
                v = bad4[c] ? -INFINITY : lo * (ALPHA_F * rqv[2] * rk4[c]);
                lse_fold(m4[2], s4[2], v);
                v = bad4[c] ? -INFINITY : hi * (ALPHA_F * rqv[3] * rk4[c]);
                lse_fold(m4[3], s4[3], v);
            }
        }

        // merge (m,s) across the 32 lanes of the warp; sum the 4 row lses
        float rowsum = 0.0f;
#pragma unroll
        for (int a = 0; a < 4; a++) {
            float m = m4[a], s = s4[a];
#pragma unroll
            for (int off = 16; off; off >>= 1) {
                float mo = __shfl_xor_sync(0xffffffffu, m, off);
                float so = __shfl_xor_sync(0xffffffffu, s, off);
                float mn = fmaxf(m, mo);
                if (mn == -INFINITY) {
                    m = -INFINITY;
                    s = 0.0f;
                } else {
                    s = s * __expf(m - mn) + so * __expf(mo - mn);
                    m = mn;
                }
            }
            rowsum += (m == -INFINITY) ? -INFINITY : (m + __logf(s));
        }
        if (lane == 0) wsum[w] = rowsum;
        // barrier + "did any lane see an unmasked j" in one op
        int ok = __syncthreads_or(my_clear);
        if (tid == 0 && ok) {
            float tot = wsum[0] + wsum[1] + wsum[2] + wsum[3];
            atomicAdd(&out[b * OO + o], (tot / ALPHA_F) * outscale);
        }
        // if !ok: every j masked -> reference result is exactly 0; out keeps
        // its prep-zeroed value (both halves agree).
    }
}

// ---------------- launch ----------------
extern "C" void kernel_launch(void* const* d_in, const int* in_sizes, int n_in,
                              void* d_out, int out_size) {
    const float* q = (const float*)d_in[0];
    const float* k = (const float*)d_in[1];
    const void* qm = d_in[2];
    const void* km = d_in[3];
    const float* ls = (const float*)d_in[4];
    float* out = (float*)d_out;

    prep_kernel<<<PREP_BLOCKS, 256>>>(q, k, qm, km, out);

    // qs2 8 pairs*128*8B = 8192 + ks 128*132*4 = 67584 -> 75776 B (3 CTAs/SM)
    size_t smem = 8192 + (size_t)128 * KST * sizeof(float);
    cudaFuncSetAttribute(score_kernel,
                         cudaFuncAttributeMaxDynamicSharedMemorySize,
                         (int)smem);
    score_kernel<<<SCORE_BLOCKS, 128, smem>>>(q, k, qm, km, ls, out);
}